// round 7
// baseline (speedup 1.0000x reference)
#include <cuda_runtime.h>
#include <cstddef>

#define KC 32
#define NCELL 512           // 8x8x8 cells per batch
#define NB 4
#define CELL_H 0.125f
#define NBR_CAP 512

// -------- scratch (fixed problem sizes: N2=16384, N1=65536, Cout=64) --------
__device__ float g_y2t[16384 * 192];   // y2 transposed: [N2][C*3]
__device__ int   g_idx[65536 * 3];
__device__ float g_w  [65536 * 3];

__device__ int    g_cnt[2 * NB * NCELL];
__device__ int    g_off[2 * NB * NCELL];
__device__ int    g_cur[2 * NB * NCELL];
__device__ float4 g_pts [16384];
__device__ float4 g_qpts[65536];
__device__ float4 g_nbrpts[NB * NCELL * NBR_CAP];  // per-cell 27-nbr candidate lists
__device__ int    g_nbrcnt[NB * NCELL];

// ---------------------------------------------------------------------------
__device__ __forceinline__ int cell_of(float x, float y, float z) {
    int cx = min((int)(x * 8.0f), 7);
    int cy = min((int)(y * 8.0f), 7);
    int cz = min((int)(z * 8.0f), 7);
    return (cz << 6) + (cy << 3) + cx;
}

__global__ void zero_kernel() {
    int i = blockIdx.x * blockDim.x + threadIdx.x;
    if (i < 2 * NB * NCELL) g_cnt[i] = 0;
}

__global__ void count_kernel(const float* __restrict__ p2,
                             const float* __restrict__ p1,
                             int n2, int N2, int n1, int N1)
{
    int i = blockIdx.x * blockDim.x + threadIdx.x;
    if (i < N2) {
        float x = p2[3*i], y = p2[3*i+1], z = p2[3*i+2];
        atomicAdd(&g_cnt[(i / n2) * NCELL + cell_of(x, y, z)], 1);
    }
    int j = i - N2;
    if (j >= 0 && j < N1) {
        float x = p1[3*j], y = p1[3*j+1], z = p1[3*j+2];
        atomicAdd(&g_cnt[(NB + j / n1) * NCELL + cell_of(x, y, z)], 1);
    }
}

__global__ __launch_bounds__(512)
void scan_kernel() {
    __shared__ int sc[NCELL];
    int b = blockIdx.x, t = threadIdx.x;
    sc[t] = g_cnt[b * NCELL + t];
    __syncthreads();
    int v = sc[t];
#pragma unroll
    for (int d = 1; d < NCELL; d <<= 1) {
        int add = (t >= d) ? sc[t - d] : 0;
        __syncthreads();
        sc[t] = v = v + add;
        __syncthreads();
    }
    int excl = v - g_cnt[b * NCELL + t];
    g_off[b * NCELL + t] = excl;
    g_cur[b * NCELL + t] = excl;
}

__global__ void scatter_kernel(const float* __restrict__ p2,
                               const float* __restrict__ p1,
                               int n2, int N2, int n1, int N1)
{
    int i = blockIdx.x * blockDim.x + threadIdx.x;
    if (i < N2) {
        float x = p2[3*i], y = p2[3*i+1], z = p2[3*i+2];
        int batch = i / n2;
        int slot = atomicAdd(&g_cur[batch * NCELL + cell_of(x, y, z)], 1);
        g_pts[batch * n2 + slot] = make_float4(x, y, z, __int_as_float(i));
    }
    int j = i - N2;
    if (j >= 0 && j < N1) {
        float x = p1[3*j], y = p1[3*j+1], z = p1[3*j+2];
        int batch = j / n1;
        int slot = atomicAdd(&g_cur[(NB + batch) * NCELL + cell_of(x, y, z)], 1);
        g_qpts[batch * n1 + slot] = make_float4(x, y, z, __int_as_float(j));
    }
}

// one block per cell: gather the 27-neighborhood candidate list contiguously
__global__ __launch_bounds__(128)
void nbr_build_kernel(int n2)
{
    __shared__ int s_src[27], s_cnt[27], s_start[27], s_total;
    int cell = blockIdx.x;
    int batch = cell >> 9, cc = cell & (NCELL - 1);
    int cx = cc & 7, cy = (cc >> 3) & 7, cz = cc >> 6;
    if (threadIdx.x == 0) {
        int tot = 0, k = 0;
        for (int z = max(cz-1,0); z <= min(cz+1,7); z++)
            for (int y = max(cy-1,0); y <= min(cy+1,7); y++)
                for (int x = max(cx-1,0); x <= min(cx+1,7); x++) {
                    int c = batch * NCELL + (z << 6) + (y << 3) + x;
                    s_src[k] = g_off[c]; s_cnt[k] = g_cnt[c]; s_start[k] = tot;
                    tot += g_cnt[c]; k++;
                }
        for (; k < 27; k++) s_cnt[k] = 0;
        s_total = tot;
        g_nbrcnt[cell] = tot;
    }
    __syncthreads();
    if (s_total > NBR_CAP) return;
    const int pbase = batch * n2;
    float4* dst = g_nbrpts + (size_t)cell * NBR_CAP;
    for (int k = 0; k < 27; k++) {
        int cnt = s_cnt[k], st = s_start[k], src = pbase + s_src[k];
        for (int j = threadIdx.x; j < cnt; j += 128)
            dst[st + j] = g_pts[src + j];
    }
}

#define KNN_INS3(d2, jj)                                                      \
    if ((d2) < e2) {                                                          \
        if ((d2) < e1) {                                                      \
            e2 = e1; j2 = j1;                                                 \
            if ((d2) < e0) { e1 = e0; j1 = j0; e0 = (d2); j0 = (jj); }        \
            else           { e1 = (d2); j1 = (jj); }                          \
        } else { e2 = (d2); j2 = (jj); }                                      \
    }

// kNN: linear scan of the prebuilt cell list (warp-coherent broadcast loads),
// rare fallback to expanding Chebyshev shells. Provably exact top-3.
__global__ __launch_bounds__(256)
void knn_kernel(int n1, int n2, int N1)
{
    int i = blockIdx.x * blockDim.x + threadIdx.x;
    if (i >= N1) return;
    float4 qp = g_qpts[i];
    const float qx = qp.x, qy = qp.y, qz = qp.z;
    const int q = __float_as_int(qp.w);
    const int batch = i / n1;
    const int cbase = batch * NCELL;
    const int pbase = batch * n2;

    const int cx = min((int)(qx * 8.0f), 7);
    const int cy = min((int)(qy * 8.0f), 7);
    const int cz = min((int)(qz * 8.0f), 7);
    const int cell = cbase + (cz << 6) + (cy << 3) + cx;

    float e0 = 3.4e38f, e1 = 3.4e38f, e2 = 3.4e38f;
    int j0 = 0, j1 = 0, j2 = 0;

    const int cnt = g_nbrcnt[cell];
    int Rstart = 2;
    if (cnt <= NBR_CAP) {
        const float4* lst = g_nbrpts + (size_t)cell * NBR_CAP;
        for (int t = 0; t < cnt; t++) {
            float4 pt = lst[t];
            float dx = qx - pt.x, dy = qy - pt.y, dz = qz - pt.z;
            float d2 = fmaf(dz, dz, fmaf(dy, dy, dx*dx));
            KNN_INS3(d2, __float_as_int(pt.w))
        }
    } else Rstart = 1;

    if (!(Rstart == 2 && e2 <= 0.999f * CELL_H * CELL_H)) {
        for (int R = Rstart; R <= 8; R++) {
            const int zlo = max(cz - R, 0), zhi = min(cz + R, 7);
            const int ylo = max(cy - R, 0), yhi = min(cy + R, 7);
            const int xlo = max(cx - R, 0), xhi = min(cx + R, 7);
            for (int z = zlo; z <= zhi; z++) {
                int az = abs(z - cz);
                for (int y = ylo; y <= yhi; y++) {
                    int ay = max(az, abs(y - cy));
                    for (int x = xlo; x <= xhi; x++) {
                        int cd = max(ay, abs(x - cx));
                        if ((R == 1) ? (cd > 1) : (cd != R)) continue;
                        int c = cbase + (z << 6) + (y << 3) + x;
                        int s = g_off[c];
                        int e = s + g_cnt[c];
                        for (int t = s; t < e; t++) {
                            float4 pt = g_pts[pbase + t];
                            float dx = qx - pt.x, dy = qy - pt.y, dz = qz - pt.z;
                            float d2 = fmaf(dz, dz, fmaf(dy, dy, dx*dx));
                            KNN_INS3(d2, __float_as_int(pt.w))
                        }
                    }
                }
            }
            float rad = (float)R * CELL_H;
            if (e2 <= 0.999f * rad * rad) break;
        }
    }

    float w0 = 1.f / (e0 + 1e-8f);
    float w1 = 1.f / (e1 + 1e-8f);
    float w2 = 1.f / (e2 + 1e-8f);
    float inv = 1.f / (w0 + w1 + w2);
    g_idx[q*3 + 0] = j0;  g_w[q*3 + 0] = w0 * inv;
    g_idx[q*3 + 1] = j1;  g_w[q*3 + 1] = w1 * inv;
    g_idx[q*3 + 2] = j2;  g_w[q*3 + 2] = w2 * inv;
}

// ---------------------------------------------------------------------------
// VN layer2 (Cin=128): x2 -> g_y2t transposed. Same structure as R5.
// ---------------------------------------------------------------------------
__global__ __launch_bounds__(256, 3)
void vn2_kernel(const float* __restrict__ x, const float* __restrict__ wfeat,
                const float* __restrict__ wdir, int N)
{
    __shared__ __align__(16) float swf[KC * 68];
    __shared__ __align__(16) float swd[KC * 68];
    __shared__ __align__(16) float xs [96 * 33];

    const int tid = threadIdx.x;
    const int g = tid & 15;
    const int o_base  = g * 4;
    const int pt_base = (tid >> 4) * 2;
    const int n0 = blockIdx.x * 32;
    const int lane = tid & 31;
    const int wrow = tid >> 5;

    float p[24], q[24];
#pragma unroll
    for (int i = 0; i < 24; i++) { p[i] = 0.f; q[i] = 0.f; }

    for (int c0 = 0; c0 < 128; c0 += KC) {
        __syncthreads();
        for (int i = tid; i < 64 * KC; i += 256) {
            int o  = i >> 5;
            int cc = i & 31;
            swf[cc*68 + o] = wfeat[o*128 + c0 + cc];
            swd[cc*68 + o] = wdir [o*128 + c0 + cc];
        }
        const float* xg = x + (size_t)(c0 * 3) * N + n0;
        for (int r = wrow; r < KC * 3; r += 8)
            xs[r * 32 + lane] = xg[(size_t)r * N + lane];
        __syncthreads();

#pragma unroll 8
        for (int cc = 0; cc < KC; ++cc) {
            const float4 f4 = *reinterpret_cast<const float4*>(&swf[cc*68 + o_base]);
            const float4 g4 = *reinterpret_cast<const float4*>(&swd[cc*68 + o_base]);
            const float2 xa = *reinterpret_cast<const float2*>(&xs[(cc*3+0)*32 + pt_base]);
            const float2 xb = *reinterpret_cast<const float2*>(&xs[(cc*3+1)*32 + pt_base]);
            const float2 xc = *reinterpret_cast<const float2*>(&xs[(cc*3+2)*32 + pt_base]);
            float wf[4] = { f4.x, f4.y, f4.z, f4.w };
            float wg[4] = { g4.x, g4.y, g4.z, g4.w };
            float xv[2][3] = { { xa.x, xb.x, xc.x }, { xa.y, xb.y, xc.y } };
#pragma unroll
            for (int i = 0; i < 4; i++)
#pragma unroll
                for (int k = 0; k < 2; k++)
#pragma unroll
                    for (int v = 0; v < 3; v++) {
                        p[(i*2+k)*3+v] = fmaf(wf[i], xv[k][v], p[(i*2+k)*3+v]);
                        q[(i*2+k)*3+v] = fmaf(wg[i], xv[k][v], q[(i*2+k)*3+v]);
                    }
        }
    }

#pragma unroll
    for (int i = 0; i < 4; i++)
#pragma unroll
        for (int k = 0; k < 2; k++) {
            const int sb = (i*2 + k) * 3;
            float px = p[sb], py = p[sb+1], pz = p[sb+2];
            float dx = q[sb], dy = q[sb+1], dz = q[sb+2];
            float dot = px*dx + py*dy + pz*dz;
            if (dot < 0.f) {
                float d2 = dx*dx + dy*dy + dz*dz;
                float t = 0.8f * dot / (d2 + 1e-6f);
                p[sb]   = px - t*dx;
                p[sb+1] = py - t*dy;
                p[sb+2] = pz - t*dz;
            }
        }

#pragma unroll
    for (int k = 0; k < 2; k++) {
        float* dst = g_y2t + (size_t)(n0 + pt_base + k) * 192 + o_base * 3;
#pragma unroll
        for (int i = 0; i < 4; i++)
#pragma unroll
            for (int v = 0; v < 3; v++)
                dst[i*3 + v] = p[(i*2+k)*3 + v];
    }
}

// ---------------------------------------------------------------------------
// VN layer1 (Cin=64) + fused 3-NN interp. Multi-tile per block: all weights
// (both 32-chunks) resident in smem once; 4 tiles of 32 points per block.
// ---------------------------------------------------------------------------
#define TILES 4
__global__ __launch_bounds__(256, 3)
void vn1_kernel(const float* __restrict__ x, const float* __restrict__ wfeat,
                const float* __restrict__ wdir, int N, float* __restrict__ out)
{
    __shared__ __align__(16) float swf[64 * 68];
    __shared__ __align__(16) float swd[64 * 68];
    __shared__ __align__(16) float xs [96 * 33];
    __shared__ int   sidx[32 * 3];
    __shared__ float swt [32 * 3];

    const int tid = threadIdx.x;
    const int g = tid & 15;
    const int o_base  = g * 4;
    const int pt_base = (tid >> 4) * 2;
    const int lane = tid & 31;
    const int wrow = tid >> 5;

    // stage ALL weights once per block
    for (int i = tid; i < 64 * 64; i += 256) {
        int o  = i >> 6;
        int cc = i & 63;
        swf[cc*68 + o] = wfeat[o*64 + cc];
        swd[cc*68 + o] = wdir [o*64 + cc];
    }

    for (int t = 0; t < TILES; t++) {
        const int n0 = (blockIdx.x * TILES + t) * 32;
        __syncthreads();                       // xs/sidx safe to overwrite
        if (tid < 96) {
            sidx[tid] = g_idx[n0*3 + tid];
            swt[tid]  = g_w[n0*3 + tid];
        }

        float p[24], q[24];
#pragma unroll
        for (int i = 0; i < 24; i++) { p[i] = 0.f; q[i] = 0.f; }

        for (int c0 = 0; c0 < 64; c0 += KC) {
            if (c0) __syncthreads();
            const float* xg = x + (size_t)(c0 * 3) * N + n0;
            for (int r = wrow; r < KC * 3; r += 8)
                xs[r * 32 + lane] = xg[(size_t)r * N + lane];
            __syncthreads();

#pragma unroll 8
            for (int cc = 0; cc < KC; ++cc) {
                const float4 f4 = *reinterpret_cast<const float4*>(&swf[(c0+cc)*68 + o_base]);
                const float4 g4 = *reinterpret_cast<const float4*>(&swd[(c0+cc)*68 + o_base]);
                const float2 xa = *reinterpret_cast<const float2*>(&xs[(cc*3+0)*32 + pt_base]);
                const float2 xb = *reinterpret_cast<const float2*>(&xs[(cc*3+1)*32 + pt_base]);
                const float2 xc = *reinterpret_cast<const float2*>(&xs[(cc*3+2)*32 + pt_base]);
                float wf[4] = { f4.x, f4.y, f4.z, f4.w };
                float wg[4] = { g4.x, g4.y, g4.z, g4.w };
                float xv[2][3] = { { xa.x, xb.x, xc.x }, { xa.y, xb.y, xc.y } };
#pragma unroll
                for (int i = 0; i < 4; i++)
#pragma unroll
                    for (int k = 0; k < 2; k++)
#pragma unroll
                        for (int v = 0; v < 3; v++) {
                            p[(i*2+k)*3+v] = fmaf(wf[i], xv[k][v], p[(i*2+k)*3+v]);
                            q[(i*2+k)*3+v] = fmaf(wg[i], xv[k][v], q[(i*2+k)*3+v]);
                        }
            }
        }

        // VN leaky-ReLU
#pragma unroll
        for (int i = 0; i < 4; i++)
#pragma unroll
            for (int k = 0; k < 2; k++) {
                const int sb = (i*2 + k) * 3;
                float px = p[sb], py = p[sb+1], pz = p[sb+2];
                float dx = q[sb], dy = q[sb+1], dz = q[sb+2];
                float dot = px*dx + py*dy + pz*dz;
                if (dot < 0.f) {
                    float d2 = dx*dx + dy*dy + dz*dz;
                    float tt = 0.8f * dot / (d2 + 1e-6f);
                    p[sb]   = px - tt*dx;
                    p[sb+1] = py - tt*dy;
                    p[sb+2] = pz - tt*dz;
                }
            }

        // fused 3-NN interpolation add from L2-resident g_y2t
#pragma unroll
        for (int k = 0; k < 2; k++) {
            const int pt = pt_base + k;
#pragma unroll
            for (int kk = 0; kk < 3; kk++) {
                const int row = sidx[pt*3 + kk];
                const float w = swt[pt*3 + kk];
                const float4* src = reinterpret_cast<const float4*>(
                    g_y2t + (size_t)row * 192 + o_base * 3);
                float4 A = src[0], B = src[1], C = src[2];
                p[ 0 + 3*k + 0] += w * A.x;
                p[ 0 + 3*k + 1] += w * A.y;
                p[ 0 + 3*k + 2] += w * A.z;
                p[ 6 + 3*k + 0] += w * A.w;
                p[ 6 + 3*k + 1] += w * B.x;
                p[ 6 + 3*k + 2] += w * B.y;
                p[12 + 3*k + 0] += w * B.z;
                p[12 + 3*k + 1] += w * B.w;
                p[12 + 3*k + 2] += w * C.x;
                p[18 + 3*k + 0] += w * C.y;
                p[18 + 3*k + 1] += w * C.z;
                p[18 + 3*k + 2] += w * C.w;
            }
        }
        // coalesced store via smem transpose (two 96-row halves)
        __syncthreads();
        if (g < 8) {
#pragma unroll
            for (int i = 0; i < 4; i++)
#pragma unroll
                for (int k = 0; k < 2; k++)
#pragma unroll
                    for (int v = 0; v < 3; v++)
                        xs[((o_base + i)*3 + v)*33 + pt_base + k] = p[(i*2+k)*3+v];
        }
        __syncthreads();
        for (int r = wrow; r < 96; r += 8)
            out[(size_t)r * N + n0 + lane] = xs[r*33 + lane];
        __syncthreads();
        if (g >= 8) {
#pragma unroll
            for (int i = 0; i < 4; i++)
#pragma unroll
                for (int k = 0; k < 2; k++)
#pragma unroll
                    for (int v = 0; v < 3; v++)
                        xs[((o_base + i)*3 + v - 96)*33 + pt_base + k] = p[(i*2+k)*3+v];
        }
        __syncthreads();
        for (int r = wrow; r < 96; r += 8)
            out[(size_t)(96 + r) * N + n0 + lane] = xs[r*33 + lane];
    }
}

// ---------------------------------------------------------------------------
extern "C" void kernel_launch(void* const* d_in, const int* in_sizes, int n_in,
                              void* d_out, int out_size)
{
    (void)n_in; (void)out_size;
    const float* p1  = (const float*)d_in[0];
    const float* x1  = (const float*)d_in[1];
    const float* p2  = (const float*)d_in[3];
    const float* x2  = (const float*)d_in[4];
    const float* w1f = (const float*)d_in[6];
    const float* w1d = (const float*)d_in[7];
    const float* w2f = (const float*)d_in[8];
    const float* w2d = (const float*)d_in[9];

    const int b  = in_sizes[2];
    const int N1 = in_sizes[0] / 3;
    const int N2 = in_sizes[3] / 3;
    const int n1 = N1 / b;
    const int n2 = N2 / b;
    float* out = (float*)d_out;

    const int NT = N2 + N1;
    zero_kernel<<<(2*NB*NCELL + 255)/256, 256>>>();
    count_kernel<<<(NT + 255)/256, 256>>>(p2, p1, n2, N2, n1, N1);
    scan_kernel<<<2*NB, 512>>>();
    scatter_kernel<<<(NT + 255)/256, 256>>>(p2, p1, n2, N2, n1, N1);
    nbr_build_kernel<<<NB*NCELL, 128>>>(n2);
    knn_kernel<<<(N1 + 255)/256, 256>>>(n1, n2, N1);

    vn2_kernel<<<N2 / 32, 256>>>(x2, w2f, w2d, N2);
    vn1_kernel<<<N1 / (32*TILES), 256>>>(x1, w1f, w1d, N1, out);
}